// round 15
// baseline (speedup 1.0000x reference)
#include <cuda_runtime.h>

#define Bsz 8
#define Ccls 5
#define Hh 512
#define Ww 512
#define HW 262144      // 512*512
#define BHW 2097152    // 8*HW
#define CF 32
#define Dd 256
#define FG 1
#define MAXT 1024
#define MAXO 4096
#define NROWS 5120
#define NSCAN 2048     // 1024-px blocks
#define NCH 80         // 64-wide column tiles in tiny-loss
#define L2E 1.4426950408889634f
#define K10 14.426950408889634f   // 10 * log2(e)

// ---------------- scratch ----------------
__device__ double g_acc[18];        // 0 ce,1 focal,2..6 probsum,7..11 inter,12..16 cnt,17 grad
__device__ float  g_sb[NSCAN * 17];
__device__ float  g_predfg[BHW];
__device__ int    g_blockcnt[NSCAN];
__device__ int    g_blockpref[NSCAN];
__device__ int    g_flags[Bsz];
__device__ int    g_nT, g_nO, g_enabled;
__device__ int    g_tinyIdx[MAXT];
__device__ int    g_otherIdx[MAXO];
__device__ float  g_cols[NROWS * CF];
__device__ float  g_part1[NCH * MAXT];   // per (colTile, row) partial exp-sums
__device__ int    g_ctr1 = 0;

#define WSUM(v) { _Pragma("unroll") for (int _o = 16; _o; _o >>= 1) v += __shfl_xor_sync(0xffffffffu, v, _o); }
#define FMA2(acc, a, b) asm("fma.rn.f32x2 %0, %1, %2, %0;" : "+l"(acc) : "l"(a), "l"(b))
#define PACK2(out, v)   asm("mov.b64 %0, {%1, %1};" : "=l"(out) : "f"(v))

// ================ pass 1: softmax stats (atomic-free) + last-block scan ================
__global__ __launch_bounds__(256) void k_stats(const float* __restrict__ logits,
                                               const int* __restrict__ tgt) {
    int blk = blockIdx.x;
    int b = blk >> 8;
    int hwBase = (blk & 255) * 1024 + threadIdx.x * 4;
    const float* lb = logits + (size_t)b * Ccls * HW;
    int t = threadIdx.x, lane = t & 31, w = t >> 5;

    float4 X[5];
#pragma unroll
    for (int c = 0; c < 5; c++) X[c] = *(const float4*)(lb + c * HW + hwBase);
    int4 tv = *(const int4*)(tgt + (size_t)b * HW + hwBase);
    int tA[4] = {tv.x, tv.y, tv.z, tv.w};

    float ceA = 0.f, foA = 0.f;
    float p0 = 0.f, p1 = 0.f, p2 = 0.f, p3 = 0.f, p4 = 0.f;
    float i0 = 0.f, i1 = 0.f, i2 = 0.f, i3 = 0.f, i4 = 0.f;
    float c0 = 0.f, c1 = 0.f, c2 = 0.f, c3 = 0.f, c4 = 0.f;
    float pr[4];

#pragma unroll
    for (int k = 0; k < 4; k++) {
        float x0 = ((const float*)&X[0])[k], x1 = ((const float*)&X[1])[k],
              x2 = ((const float*)&X[2])[k], x3 = ((const float*)&X[3])[k],
              x4 = ((const float*)&X[4])[k];
        float m = fmaxf(fmaxf(fmaxf(x0, x1), fmaxf(x2, x3)), x4);
        float nm = -m * L2E;
        float e0 = exp2f(fmaf(x0, L2E, nm)), e1 = exp2f(fmaf(x1, L2E, nm)),
              e2 = exp2f(fmaf(x2, L2E, nm)), e3 = exp2f(fmaf(x3, L2E, nm)),
              e4 = exp2f(fmaf(x4, L2E, nm));
        float S = e0 + e1 + e2 + e3 + e4;
        float inv = __fdividef(1.0f, S);
        float logS = __logf(S);
        int tc = tA[k];
        float s0 = (tc == 0) ? 1.f : 0.f;
        float s1 = (tc == 1) ? 1.f : 0.f;
        float s2 = (tc == 2) ? 1.f : 0.f;
        float s3 = (tc == 3) ? 1.f : 0.f;
        float s4 = (tc == 4) ? 1.f : 0.f;
        float xt = s0 * x0 + s1 * x1 + s2 * x2 + s3 * x3 + s4 * x4;
        float et = s0 * e0 + s1 * e1 + s2 * e2 + s3 * e3 + s4 * e4;
        float ce = (m - xt) + logS;
        float pt = et * inv;
        float om = 1.0f - pt;
        ceA += ce;
        foA = fmaf(om * om, ce, foA);
        p0 = fmaf(e0, inv, p0); p1 = fmaf(e1, inv, p1); p2 = fmaf(e2, inv, p2);
        p3 = fmaf(e3, inv, p3); p4 = fmaf(e4, inv, p4);
        i0 = fmaf(s0, pt, i0); i1 = fmaf(s1, pt, i1); i2 = fmaf(s2, pt, i2);
        i3 = fmaf(s3, pt, i3); i4 = fmaf(s4, pt, i4);
        c0 += s0; c1 += s1; c2 += s2; c3 += s3; c4 += s4;
        pr[k] = e1 * inv;
    }
    *(float4*)(g_predfg + (size_t)b * HW + hwBase) = make_float4(pr[0], pr[1], pr[2], pr[3]);

    WSUM(ceA) WSUM(foA)
    WSUM(p0) WSUM(p1) WSUM(p2) WSUM(p3) WSUM(p4)
    WSUM(i0) WSUM(i1) WSUM(i2) WSUM(i3) WSUM(i4)
    WSUM(c0) WSUM(c1) WSUM(c2) WSUM(c3) WSUM(c4)

    __shared__ float swp[8][18];
    if (lane == 0) {
        float* d = swp[w];
        d[0] = ceA; d[1] = foA;
        d[2] = p0; d[3] = p1; d[4] = p2; d[5] = p3; d[6] = p4;
        d[7] = i0; d[8] = i1; d[9] = i2; d[10] = i3; d[11] = i4;
        d[12] = c0; d[13] = c1; d[14] = c2; d[15] = c3; d[16] = c4;
    }
    __syncthreads();
    if (t < 17) {
        float s = 0.f;
#pragma unroll
        for (int i = 0; i < 8; i++) s += swp[i][t];
        g_sb[blk * 17 + t] = s;
        if (t == 12 + FG) g_blockcnt[blk] = (int)(s + 0.5f);
    }

    // ---- last-block tail: scan + global reduce ----
    __threadfence();
    __shared__ int lastFlag;
    __syncthreads();
    if (t == 0) {
        int r = atomicAdd(&g_ctr1, 1);
        lastFlag = (r == NSCAN - 1);
    }
    __syncthreads();
    if (!lastFlag) return;
    if (t == 0) g_ctr1 = 0;
    __threadfence();

    __shared__ float sacc[17];
    __shared__ int simg[8], sflg[8], wsumS[8];
    if (t < 17) sacc[t] = 0.f;
    if (t < 8) simg[t] = 0;
    __syncthreads();

    float a17[17];
#pragma unroll
    for (int i = 0; i < 17; i++) a17[i] = 0.f;
#pragma unroll
    for (int k = 0; k < 8; k++) {
        int bb = t + 256 * k;
#pragma unroll
        for (int i = 0; i < 17; i++) a17[i] += g_sb[bb * 17 + i];
        int cc = g_blockcnt[bb];
        WSUM(cc)
        if (lane == 0) atomicAdd(&simg[k], cc);
    }
#pragma unroll
    for (int i = 0; i < 17; i++) { float v = a17[i]; WSUM(v) if (lane == 0) atomicAdd(&sacc[i], v); }
    __syncthreads();
    if (t < 17) g_acc[t] = (double)sacc[t];
    if (t == 17) g_acc[17] = 0.0;
    if (t < 8) { sflg[t] = (simg[t] > 0 && simg[t] <= 2048) ? 1 : 0; g_flags[t] = sflg[t]; }
    __syncthreads();

    int base8 = t * 8;
    int f = sflg[base8 >> 8];
    int ex[8]; int run = 0;
#pragma unroll
    for (int k = 0; k < 8; k++) { ex[k] = run; int v = f ? g_blockcnt[base8 + k] : 0; run += v; }
    int s = run;
#pragma unroll
    for (int off = 1; off < 32; off <<= 1) {
        int u = __shfl_up_sync(0xffffffffu, s, off);
        if (lane >= off) s += u;
    }
    if (lane == 31) wsumS[w] = s;
    __syncthreads();
    int wb = 0;
#pragma unroll
    for (int i = 0; i < 8; i++) wb += (i < w) ? wsumS[i] : 0;
    int excl = wb + s - run;
#pragma unroll
    for (int k = 0; k < 8; k++) g_blockpref[base8 + k] = excl + ex[k];
    if (t == 255) {
        int tot = wb + s;
        g_nT = tot < MAXT ? tot : MAXT;
        int oth = BHW - tot;
        g_nO = oth < MAXO ? oth : MAXO;
        int any = sflg[0] | sflg[1] | sflg[2] | sflg[3] | sflg[4] | sflg[5] | sflg[6] | sflg[7];
        g_enabled = (any && tot >= 16) ? 1 : 0;
    }
}

// ================ pass 2: fused sobel + scatter ================
__global__ __launch_bounds__(256) void k_ss(const int* __restrict__ tgt) {
    __shared__ float spf[4][514];
    __shared__ float stf[4][514];
    __shared__ int wscan[8];
    __shared__ float sgrad[8];
    int sb = blockIdx.x;
    int b = sb >> 8;
    int r0 = (sb & 255) * 2;
    const float* pfb = g_predfg + (size_t)b * HW;
    const int* tb = tgt + (size_t)b * HW;
    int t = threadIdx.x, lane = t & 31, w = t >> 5;

    if (t < 8) { spf[t & 3][(t < 4) ? 0 : 513] = 0.f; stf[t & 3][(t < 4) ? 0 : 513] = 0.f; }
    {
        int lr = t >> 6;
        int c8 = (t & 63) * 8;
        int gr = r0 - 1 + lr;
        float4 pA = {0, 0, 0, 0}, pB = pA, fA = pA, fB = pA;
        if (gr >= 0 && gr < Hh) {
            const float4* prow = (const float4*)(pfb + gr * Ww + c8);
            pA = prow[0]; pB = prow[1];
            const int4* trow = (const int4*)(tb + gr * Ww + c8);
            int4 u0 = trow[0], u1 = trow[1];
            fA = make_float4(u0.x > 0 ? 1.f : 0.f, u0.y > 0 ? 1.f : 0.f,
                             u0.z > 0 ? 1.f : 0.f, u0.w > 0 ? 1.f : 0.f);
            fB = make_float4(u1.x > 0 ? 1.f : 0.f, u1.y > 0 ? 1.f : 0.f,
                             u1.z > 0 ? 1.f : 0.f, u1.w > 0 ? 1.f : 0.f);
        }
        float* dp = &spf[lr][1 + c8];
        dp[0] = pA.x; dp[1] = pA.y; dp[2] = pA.z; dp[3] = pA.w;
        dp[4] = pB.x; dp[5] = pB.y; dp[6] = pB.z; dp[7] = pB.w;
        float* df = &stf[lr][1 + c8];
        df[0] = fA.x; df[1] = fA.y; df[2] = fA.z; df[3] = fA.w;
        df[4] = fB.x; df[5] = fB.y; df[6] = fB.z; df[7] = fB.w;
    }
    __syncthreads();

    int local = t * 4;
    int lrow = 1 + (local >> 9);
    int col0 = local & 511;
    float dsum = 0.f;
#pragma unroll
    for (int k = 0; k < 4; k++) {
        int c = col0 + k + 1;
        float p00 = spf[lrow - 1][c - 1], p01 = spf[lrow - 1][c], p02 = spf[lrow - 1][c + 1];
        float p10 = spf[lrow][c - 1],                             p12 = spf[lrow][c + 1];
        float p20 = spf[lrow + 1][c - 1], p21 = spf[lrow + 1][c], p22 = spf[lrow + 1][c + 1];
        float gxp = (p02 + 2.f * p12 + p22) - (p00 + 2.f * p10 + p20);
        float gyp = (p20 + 2.f * p21 + p22) - (p00 + 2.f * p01 + p02);
        float q00 = stf[lrow - 1][c - 1], q01 = stf[lrow - 1][c], q02 = stf[lrow - 1][c + 1];
        float q10 = stf[lrow][c - 1],                             q12 = stf[lrow][c + 1];
        float q20 = stf[lrow + 1][c - 1], q21 = stf[lrow + 1][c], q22 = stf[lrow + 1][c + 1];
        float gxt = (q02 + 2.f * q12 + q22) - (q00 + 2.f * q10 + q20);
        float gyt = (q20 + 2.f * q21 + q22) - (q00 + 2.f * q01 + q02);
        float sp = sqrtf(fmaf(gxp, gxp, gyp * gyp) + 1e-6f);
        float st = sqrtf(fmaf(gxt, gxt, gyt * gyt) + 1e-6f);
        dsum += fabsf(sp - st);
    }
    WSUM(dsum)
    if (lane == 0) sgrad[w] = dsum;

    int prefT = g_blockpref[sb];
    int prefO = sb * 1024 - prefT;
    int nT = g_nT, nO = g_nO;
    int flag = g_flags[b];
    int4 tv = *(const int4*)(tb + r0 * Ww + t * 4);
    int m0 = (tv.x == FG && flag) ? 1 : 0;
    int m1 = (tv.y == FG && flag) ? 1 : 0;
    int m2 = (tv.z == FG && flag) ? 1 : 0;
    int m3 = (tv.w == FG && flag) ? 1 : 0;
    int cnt = m0 + m1 + m2 + m3;
    int s = cnt;
#pragma unroll
    for (int off = 1; off < 32; off <<= 1) {
        int u = __shfl_up_sync(0xffffffffu, s, off);
        if (lane >= off) s += u;
    }
    if (lane == 31) wscan[w] = s;
    __syncthreads();
    int wbase = 0;
#pragma unroll
    for (int i = 0; i < 8; i++) wbase += (i < w) ? wscan[i] : 0;
    int myExcl = wbase + s - cnt;
    if (prefT < nT || prefO < nO) {
        int tb2 = prefT + myExcl;
        int ob = prefO + t * 4 - myExcl;
        int p = sb * 1024 + t * 4;
        if (m0) { if (tb2 < nT) g_tinyIdx[tb2] = p; tb2++; } else { if (ob < nO) g_otherIdx[ob] = p; ob++; }
        p++;
        if (m1) { if (tb2 < nT) g_tinyIdx[tb2] = p; tb2++; } else { if (ob < nO) g_otherIdx[ob] = p; ob++; }
        p++;
        if (m2) { if (tb2 < nT) g_tinyIdx[tb2] = p; tb2++; } else { if (ob < nO) g_otherIdx[ob] = p; ob++; }
        p++;
        if (m3) { if (tb2 < nT) g_tinyIdx[tb2] = p; tb2++; } else { if (ob < nO) g_otherIdx[ob] = p; ob++; }
    }
    if (t == 0) {
        float g = sgrad[0] + sgrad[1] + sgrad[2] + sgrad[3]
                + sgrad[4] + sgrad[5] + sgrad[6] + sgrad[7];
        atomicAdd(&g_acc[17], (double)g);
    }
}

// ================ pass 3: gather + l2norm (4 rows/warp, batched MLP) ================
__global__ __launch_bounds__(256) void k_gather(const float* __restrict__ pf) {
    int warp = threadIdx.x >> 5, lane = threadIdx.x & 31;
    int rbase = (blockIdx.x * 8 + warp) * 4;
    int nT = g_nT, nO = g_nO;
    int idx[4]; float v[4];
#pragma unroll
    for (int k = 0; k < 4; k++) {
        int r = rbase + k;
        int id = -1;
        if (r < MAXT) { if (r < nT) id = g_tinyIdx[r]; }
        else { int j = r - MAXT; if (j < nO) id = g_otherIdx[j]; }
        idx[k] = id;
    }
#pragma unroll
    for (int k = 0; k < 4; k++) {
        int id = idx[k];
        v[k] = (id >= 0) ? pf[(size_t)((id >> 18) * CF + lane) * HW + (id & (HW - 1))] : 0.f;
    }
#pragma unroll
    for (int k = 0; k < 4; k++) {
        float sq = v[k] * v[k];
        WSUM(sq)
        g_cols[(rbase + k) * CF + lane] = v[k] / fmaxf(sqrtf(sq), 1e-12f);   // invalid rows -> 0
    }
}

// ================ pass 4: tiny contrastive — 128x64 tiles, software-pipelined k-loop ================
// grid (8 row-tiles, 80 col-tiles) = 640 blocks. 128 thr = 16(ty) x 8(tx).
__global__ __launch_bounds__(128) void k_tinyloss() {
    __shared__ float As[32][128];      // [k][row] 16KB
    __shared__ float Bs[32][64];       // [k][col] 8KB
    __shared__ float red[128][8];      // row-sum staging 4KB
    int tid = threadIdx.x;
    int rbase = blockIdx.x * 128;
    int cbase = blockIdx.y * 64;

    // stage A (128 rows) transposed: 1024 float4, 8 reps
#pragma unroll
    for (int rep = 0; rep < 8; rep++) {
        int idx = rep * 128 + tid;
        int r = idx >> 3, q = idx & 7;
        float4 va = *(const float4*)(g_cols + (rbase + r) * CF + q * 4);
        As[q * 4 + 0][r] = va.x; As[q * 4 + 1][r] = va.y;
        As[q * 4 + 2][r] = va.z; As[q * 4 + 3][r] = va.w;
    }
    // stage B (64 cols) transposed: 512 float4, 4 reps
#pragma unroll
    for (int rep = 0; rep < 4; rep++) {
        int idx = rep * 128 + tid;
        int r = idx >> 3, q = idx & 7;
        float4 vb = *(const float4*)(g_cols + (cbase + r) * CF + q * 4);
        Bs[q * 4 + 0][r] = vb.x; Bs[q * 4 + 1][r] = vb.y;
        Bs[q * 4 + 2][r] = vb.z; Bs[q * 4 + 3][r] = vb.w;
    }
    __syncthreads();

    int tx = tid & 7, ty = tid >> 3;
    unsigned long long acc[8][4];
#pragma unroll
    for (int i = 0; i < 8; i++)
#pragma unroll
        for (int j = 0; j < 4; j++) acc[i][j] = 0ull;

    // software pipeline: prefetch k+1 operands while computing k
    float4 aA = *(const float4*)&As[0][ty * 8];
    float4 aB = *(const float4*)&As[0][ty * 8 + 4];
    ulonglong2 b0 = *(const ulonglong2*)&Bs[0][tx * 8];
    ulonglong2 b1 = *(const ulonglong2*)&Bs[0][tx * 8 + 4];

#pragma unroll
    for (int k = 0; k < 32; k++) {
        float4 naA, naB;
        ulonglong2 nb0, nb1;
        if (k < 31) {
            naA = *(const float4*)&As[k + 1][ty * 8];
            naB = *(const float4*)&As[k + 1][ty * 8 + 4];
            nb0 = *(const ulonglong2*)&Bs[k + 1][tx * 8];
            nb1 = *(const ulonglong2*)&Bs[k + 1][tx * 8 + 4];
        }
        float av[8] = {aA.x, aA.y, aA.z, aA.w, aB.x, aB.y, aB.z, aB.w};
#pragma unroll
        for (int i = 0; i < 8; i++) {
            unsigned long long a2;
            PACK2(a2, av[i]);
            FMA2(acc[i][0], a2, b0.x);
            FMA2(acc[i][1], a2, b0.y);
            FMA2(acc[i][2], a2, b1.x);
            FMA2(acc[i][3], a2, b1.y);
        }
        if (k < 31) { aA = naA; aB = naB; b0 = nb0; b1 = nb1; }
    }

    // epilogue: exp + row-sum of this thread's 8 cols
#pragma unroll
    for (int i = 0; i < 8; i++) {
        float rs = 0.f;
#pragma unroll
        for (int j = 0; j < 4; j++) {
            float2 f = *(float2*)&acc[i][j];
            rs += exp2f(fmaf(f.x, K10, -K10));
            rs += exp2f(fmaf(f.y, K10, -K10));
        }
        red[ty * 8 + i][tx] = rs;
    }
    __syncthreads();
    {
        const float4* rp = (const float4*)&red[tid][0];
        float4 s0 = rp[0], s1 = rp[1];
        float tot = ((s0.x + s0.y) + (s0.z + s0.w)) + ((s1.x + s1.y) + (s1.z + s1.w));
        g_part1[blockIdx.y * MAXT + rbase + tid] = tot;
    }
}

// ================ pass 5: final (parallelized cls contrastive) ================
__global__ __launch_bounds__(1024) void k_final(const float* __restrict__ emb,
                                                const int* __restrict__ lab,
                                                float* __restrict__ out) {
    __shared__ float e[Bsz * Dd];
    __shared__ float dotm[Bsz * Bsz];
    __shared__ float red[32];
    __shared__ float s_per[Bsz], s_bce[Bsz];
    __shared__ int s_has[Bsz];
    int t = threadIdx.x, lane = t & 31, w = t >> 5;
    int nT = g_nT, nO = g_nO;

    float per = 0.f;
    if (t < nT) {
        float sT = 0.f, sO = 0.f;
#pragma unroll
        for (int c = 0; c < 16; c++)  sT += g_part1[c * MAXT + t];    // col tiles 0..15 = tiny (16*64=1024)
#pragma unroll 16
        for (int c = 16; c < NCH; c++) sO += g_part1[c * MAXT + t];   // col tiles 16..79 = other
        const float cz = exp2f(-K10);
        sT -= 1.0f + (float)(MAXT - nT) * cz;
        sO -= (float)(MAXO - nO) * cz;
        sT = fmaxf(sT, 1e-30f);
        per = log1pf(sO / sT);
    }

    for (int i = t; i < Bsz * Dd; i += 1024) e[i] = emb[i];
    __syncthreads();
    if (t < 256) {
        float sq = 0.f;
        for (int k = lane; k < Dd; k += 32) { float v = e[w * Dd + k]; sq += v * v; }
        WSUM(sq)
        float inv = 1.0f / fmaxf(sqrtf(sq), 1e-12f);
        for (int k = lane; k < Dd; k += 32) e[w * Dd + k] *= inv;
    }
    __syncthreads();
    if (t < 256) {
        for (int j = 0; j < Bsz; j++) {
            float d = 0.f;
            for (int k = lane; k < Dd; k += 32) d += e[w * Dd + k] * e[j * Dd + k];
            WSUM(d)
            if (lane == 0) dotm[w * Bsz + j] = d;
        }
    }
    __syncthreads();

    // parallel cls contrastive: thread i < 8 owns row i
    if (t < Bsz) {
        int i = t;
        int Li = lab[i];
        float sP = 0.f, sA = 0.f, bce = 0.f;
        int has = 0;
#pragma unroll
        for (int j = 0; j < Bsz; j++) {
            if (j == i) continue;
            float dv = dotm[i * Bsz + j];
            float wE = exp2f(fmaf(dv, K10, -K10));
            sA += wE;
            bool pos = (Li == lab[j]);
            if (pos) { has = 1; sP += wE; }
            float cosv = fminf(fmaxf(dv, -1.0f), 1.0f);
            float p01 = (cosv + 1.0f) * 0.5f;
            float l1 = fmaxf(__logf(p01), -100.0f);
            float l2 = fmaxf(__logf(1.0f - p01), -100.0f);
            bce += pos ? -l1 : -l2;
        }
        s_per[i] = has ? __logf(sA / sP) : 0.f;
        s_has[i] = has;
        s_bce[i] = bce;
    }

    WSUM(per)
    if (lane == 0) red[w] = per;
    __syncthreads();

    if (t == 0) {
        float tinySum = 0.f;
        for (int i = 0; i < 32; i++) tinySum += red[i];

        float per_sum = 0.f, bce_sum = 0.f;
        int nvalid = 0;
        for (int i = 0; i < Bsz; i++) {
            per_sum += s_per[i];
            bce_sum += s_bce[i];
            nvalid += s_has[i];
        }
        float clsv = (nvalid > 0) ? per_sum / (float)nvalid : bce_sum / 56.0f;

        double N = (double)BHW;
        double ce = g_acc[0] / N;
        double fo = g_acc[1] / N;
        double gr = g_acc[17] / N;
        double ds = 0.0;
        for (int c = 0; c < Ccls; c++) {
            double inter = g_acc[7 + c];
            double den = g_acc[2 + c] + g_acc[12 + c];
            ds += (2.0 * inter + 1e-6) / (den + 1e-6);
        }
        double dice = 1.0 - ds / 5.0;
        double tiny = 0.0;
        if (g_enabled) tiny = (double)tinySum / (double)(nT > 0 ? nT : 1);
        out[0] = (float)(ce + dice + fo + gr + tiny + (double)clsv);
    }
}

// ---------------- launch ----------------
extern "C" void kernel_launch(void* const* d_in, const int* in_sizes, int n_in,
                              void* d_out, int out_size) {
    const float* logits  = (const float*)d_in[0];
    const int*   targets = (const int*)d_in[1];
    const float* pf      = (const float*)d_in[2];
    const float* emb     = (const float*)d_in[3];
    const int*   clab    = (const int*)d_in[4];
    float* out = (float*)d_out;

    k_stats<<<NSCAN, 256>>>(logits, targets);
    k_ss<<<NSCAN, 256>>>(targets);
    k_gather<<<160, 256>>>(pf);
    k_tinyloss<<<dim3(8, NCH), 128>>>();
    k_final<<<1, 1024>>>(emb, clab, out);
}

// round 16
// speedup vs baseline: 1.0244x; 1.0244x over previous
#include <cuda_runtime.h>

#define Bsz 8
#define Ccls 5
#define Hh 512
#define Ww 512
#define HW 262144      // 512*512
#define BHW 2097152    // 8*HW
#define CF 32
#define Dd 256
#define FG 1
#define MAXT 1024
#define MAXO 4096
#define NROWS 5120
#define NSCAN 2048     // 1024-px blocks
#define NCH 80         // 64-wide column tiles in tiny-loss
#define L2E 1.4426950408889634f
#define K10 14.426950408889634f   // 10 * log2(e)

// ---------------- scratch ----------------
__device__ double g_acc[18];        // 0 ce,1 focal,2..6 probsum,7..11 inter,12..16 cnt,17 grad
__device__ float  g_sb[NSCAN * 17];
__device__ float  g_predfg[BHW];
__device__ int    g_blockcnt[NSCAN];
__device__ int    g_blockpref[NSCAN];
__device__ int    g_flags[Bsz];
__device__ int    g_nT, g_nO, g_enabled;
__device__ int    g_tinyIdx[MAXT];
__device__ int    g_otherIdx[MAXO];
__device__ float  g_cols[NROWS * CF];
__device__ float  g_part1[NCH * MAXT];   // per (colTile, row) partial exp-sums
__device__ int    g_ctr1 = 0;

#define WSUM(v) { _Pragma("unroll") for (int _o = 16; _o; _o >>= 1) v += __shfl_xor_sync(0xffffffffu, v, _o); }
#define FMA2(acc, a, b) asm("fma.rn.f32x2 %0, %1, %2, %0;" : "+l"(acc) : "l"(a), "l"(b))
#define PACK2(out, v)   asm("mov.b64 %0, {%1, %1};" : "=l"(out) : "f"(v))

// single-instruction MUFU.EX2 (2^x), bypassing libdevice accurate path
__device__ __forceinline__ float ex2(float x) {
    float r;
    asm("ex2.approx.ftz.f32 %0, %1;" : "=f"(r) : "f"(x));
    return r;
}

// ================ pass 1: softmax stats (atomic-free) + last-block scan ================
__global__ __launch_bounds__(256) void k_stats(const float* __restrict__ logits,
                                               const int* __restrict__ tgt) {
    int blk = blockIdx.x;
    int b = blk >> 8;
    int hwBase = (blk & 255) * 1024 + threadIdx.x * 4;
    const float* lb = logits + (size_t)b * Ccls * HW;
    int t = threadIdx.x, lane = t & 31, w = t >> 5;

    float4 X[5];
#pragma unroll
    for (int c = 0; c < 5; c++) X[c] = *(const float4*)(lb + c * HW + hwBase);
    int4 tv = *(const int4*)(tgt + (size_t)b * HW + hwBase);
    int tA[4] = {tv.x, tv.y, tv.z, tv.w};

    float ceA = 0.f, foA = 0.f;
    float p0 = 0.f, p1 = 0.f, p2 = 0.f, p3 = 0.f, p4 = 0.f;
    float i0 = 0.f, i1 = 0.f, i2 = 0.f, i3 = 0.f, i4 = 0.f;
    float c0 = 0.f, c1 = 0.f, c2 = 0.f, c3 = 0.f, c4 = 0.f;
    float pr[4];

#pragma unroll
    for (int k = 0; k < 4; k++) {
        float x0 = ((const float*)&X[0])[k], x1 = ((const float*)&X[1])[k],
              x2 = ((const float*)&X[2])[k], x3 = ((const float*)&X[3])[k],
              x4 = ((const float*)&X[4])[k];
        float m = fmaxf(fmaxf(fmaxf(x0, x1), fmaxf(x2, x3)), x4);
        float nm = -m * L2E;
        float e0 = ex2(fmaf(x0, L2E, nm)), e1 = ex2(fmaf(x1, L2E, nm)),
              e2 = ex2(fmaf(x2, L2E, nm)), e3 = ex2(fmaf(x3, L2E, nm)),
              e4 = ex2(fmaf(x4, L2E, nm));
        float S = e0 + e1 + e2 + e3 + e4;
        float inv = __fdividef(1.0f, S);
        float logS = __logf(S);
        int tc = tA[k];
        float s0 = (tc == 0) ? 1.f : 0.f;
        float s1 = (tc == 1) ? 1.f : 0.f;
        float s2 = (tc == 2) ? 1.f : 0.f;
        float s3 = (tc == 3) ? 1.f : 0.f;
        float s4 = (tc == 4) ? 1.f : 0.f;
        float xt = s0 * x0 + s1 * x1 + s2 * x2 + s3 * x3 + s4 * x4;
        float et = s0 * e0 + s1 * e1 + s2 * e2 + s3 * e3 + s4 * e4;
        float ce = (m - xt) + logS;
        float pt = et * inv;
        float om = 1.0f - pt;
        ceA += ce;
        foA = fmaf(om * om, ce, foA);
        p0 = fmaf(e0, inv, p0); p1 = fmaf(e1, inv, p1); p2 = fmaf(e2, inv, p2);
        p3 = fmaf(e3, inv, p3); p4 = fmaf(e4, inv, p4);
        i0 = fmaf(s0, pt, i0); i1 = fmaf(s1, pt, i1); i2 = fmaf(s2, pt, i2);
        i3 = fmaf(s3, pt, i3); i4 = fmaf(s4, pt, i4);
        c0 += s0; c1 += s1; c2 += s2; c3 += s3; c4 += s4;
        pr[k] = e1 * inv;
    }
    *(float4*)(g_predfg + (size_t)b * HW + hwBase) = make_float4(pr[0], pr[1], pr[2], pr[3]);

    WSUM(ceA) WSUM(foA)
    WSUM(p0) WSUM(p1) WSUM(p2) WSUM(p3) WSUM(p4)
    WSUM(i0) WSUM(i1) WSUM(i2) WSUM(i3) WSUM(i4)
    WSUM(c0) WSUM(c1) WSUM(c2) WSUM(c3) WSUM(c4)

    __shared__ float swp[8][18];
    if (lane == 0) {
        float* d = swp[w];
        d[0] = ceA; d[1] = foA;
        d[2] = p0; d[3] = p1; d[4] = p2; d[5] = p3; d[6] = p4;
        d[7] = i0; d[8] = i1; d[9] = i2; d[10] = i3; d[11] = i4;
        d[12] = c0; d[13] = c1; d[14] = c2; d[15] = c3; d[16] = c4;
    }
    __syncthreads();
    if (t < 17) {
        float s = 0.f;
#pragma unroll
        for (int i = 0; i < 8; i++) s += swp[i][t];
        g_sb[blk * 17 + t] = s;
        if (t == 12 + FG) g_blockcnt[blk] = (int)(s + 0.5f);
    }

    // ---- last-block tail: scan + global reduce ----
    __threadfence();
    __shared__ int lastFlag;
    __syncthreads();
    if (t == 0) {
        int r = atomicAdd(&g_ctr1, 1);
        lastFlag = (r == NSCAN - 1);
    }
    __syncthreads();
    if (!lastFlag) return;
    if (t == 0) g_ctr1 = 0;
    __threadfence();

    __shared__ float sacc[17];
    __shared__ int simg[8], sflg[8], wsumS[8];
    if (t < 17) sacc[t] = 0.f;
    if (t < 8) simg[t] = 0;
    __syncthreads();

    float a17[17];
#pragma unroll
    for (int i = 0; i < 17; i++) a17[i] = 0.f;
#pragma unroll
    for (int k = 0; k < 8; k++) {
        int bb = t + 256 * k;
#pragma unroll
        for (int i = 0; i < 17; i++) a17[i] += g_sb[bb * 17 + i];
        int cc = g_blockcnt[bb];
        WSUM(cc)
        if (lane == 0) atomicAdd(&simg[k], cc);
    }
#pragma unroll
    for (int i = 0; i < 17; i++) { float v = a17[i]; WSUM(v) if (lane == 0) atomicAdd(&sacc[i], v); }
    __syncthreads();
    if (t < 17) g_acc[t] = (double)sacc[t];
    if (t == 17) g_acc[17] = 0.0;
    if (t < 8) { sflg[t] = (simg[t] > 0 && simg[t] <= 2048) ? 1 : 0; g_flags[t] = sflg[t]; }
    __syncthreads();

    int base8 = t * 8;
    int f = sflg[base8 >> 8];
    int ex[8]; int run = 0;
#pragma unroll
    for (int k = 0; k < 8; k++) { ex[k] = run; int v = f ? g_blockcnt[base8 + k] : 0; run += v; }
    int s = run;
#pragma unroll
    for (int off = 1; off < 32; off <<= 1) {
        int u = __shfl_up_sync(0xffffffffu, s, off);
        if (lane >= off) s += u;
    }
    if (lane == 31) wsumS[w] = s;
    __syncthreads();
    int wb = 0;
#pragma unroll
    for (int i = 0; i < 8; i++) wb += (i < w) ? wsumS[i] : 0;
    int excl = wb + s - run;
#pragma unroll
    for (int k = 0; k < 8; k++) g_blockpref[base8 + k] = excl + ex[k];
    if (t == 255) {
        int tot = wb + s;
        g_nT = tot < MAXT ? tot : MAXT;
        int oth = BHW - tot;
        g_nO = oth < MAXO ? oth : MAXO;
        int any = sflg[0] | sflg[1] | sflg[2] | sflg[3] | sflg[4] | sflg[5] | sflg[6] | sflg[7];
        g_enabled = (any && tot >= 16) ? 1 : 0;
    }
}

// ================ pass 2: fused sobel + scatter ================
__global__ __launch_bounds__(256) void k_ss(const int* __restrict__ tgt) {
    __shared__ float spf[4][514];
    __shared__ float stf[4][514];
    __shared__ int wscan[8];
    __shared__ float sgrad[8];
    int sb = blockIdx.x;
    int b = sb >> 8;
    int r0 = (sb & 255) * 2;
    const float* pfb = g_predfg + (size_t)b * HW;
    const int* tb = tgt + (size_t)b * HW;
    int t = threadIdx.x, lane = t & 31, w = t >> 5;

    if (t < 8) { spf[t & 3][(t < 4) ? 0 : 513] = 0.f; stf[t & 3][(t < 4) ? 0 : 513] = 0.f; }
    {
        int lr = t >> 6;
        int c8 = (t & 63) * 8;
        int gr = r0 - 1 + lr;
        float4 pA = {0, 0, 0, 0}, pB = pA, fA = pA, fB = pA;
        if (gr >= 0 && gr < Hh) {
            const float4* prow = (const float4*)(pfb + gr * Ww + c8);
            pA = prow[0]; pB = prow[1];
            const int4* trow = (const int4*)(tb + gr * Ww + c8);
            int4 u0 = trow[0], u1 = trow[1];
            fA = make_float4(u0.x > 0 ? 1.f : 0.f, u0.y > 0 ? 1.f : 0.f,
                             u0.z > 0 ? 1.f : 0.f, u0.w > 0 ? 1.f : 0.f);
            fB = make_float4(u1.x > 0 ? 1.f : 0.f, u1.y > 0 ? 1.f : 0.f,
                             u1.z > 0 ? 1.f : 0.f, u1.w > 0 ? 1.f : 0.f);
        }
        float* dp = &spf[lr][1 + c8];
        dp[0] = pA.x; dp[1] = pA.y; dp[2] = pA.z; dp[3] = pA.w;
        dp[4] = pB.x; dp[5] = pB.y; dp[6] = pB.z; dp[7] = pB.w;
        float* df = &stf[lr][1 + c8];
        df[0] = fA.x; df[1] = fA.y; df[2] = fA.z; df[3] = fA.w;
        df[4] = fB.x; df[5] = fB.y; df[6] = fB.z; df[7] = fB.w;
    }
    __syncthreads();

    int local = t * 4;
    int lrow = 1 + (local >> 9);
    int col0 = local & 511;
    float dsum = 0.f;
#pragma unroll
    for (int k = 0; k < 4; k++) {
        int c = col0 + k + 1;
        float p00 = spf[lrow - 1][c - 1], p01 = spf[lrow - 1][c], p02 = spf[lrow - 1][c + 1];
        float p10 = spf[lrow][c - 1],                             p12 = spf[lrow][c + 1];
        float p20 = spf[lrow + 1][c - 1], p21 = spf[lrow + 1][c], p22 = spf[lrow + 1][c + 1];
        float gxp = (p02 + 2.f * p12 + p22) - (p00 + 2.f * p10 + p20);
        float gyp = (p20 + 2.f * p21 + p22) - (p00 + 2.f * p01 + p02);
        float q00 = stf[lrow - 1][c - 1], q01 = stf[lrow - 1][c], q02 = stf[lrow - 1][c + 1];
        float q10 = stf[lrow][c - 1],                             q12 = stf[lrow][c + 1];
        float q20 = stf[lrow + 1][c - 1], q21 = stf[lrow + 1][c], q22 = stf[lrow + 1][c + 1];
        float gxt = (q02 + 2.f * q12 + q22) - (q00 + 2.f * q10 + q20);
        float gyt = (q20 + 2.f * q21 + q22) - (q00 + 2.f * q01 + q02);
        float sp = sqrtf(fmaf(gxp, gxp, gyp * gyp) + 1e-6f);
        float st = sqrtf(fmaf(gxt, gxt, gyt * gyt) + 1e-6f);
        dsum += fabsf(sp - st);
    }
    WSUM(dsum)
    if (lane == 0) sgrad[w] = dsum;

    int prefT = g_blockpref[sb];
    int prefO = sb * 1024 - prefT;
    int nT = g_nT, nO = g_nO;
    int flag = g_flags[b];
    int4 tv = *(const int4*)(tb + r0 * Ww + t * 4);
    int m0 = (tv.x == FG && flag) ? 1 : 0;
    int m1 = (tv.y == FG && flag) ? 1 : 0;
    int m2 = (tv.z == FG && flag) ? 1 : 0;
    int m3 = (tv.w == FG && flag) ? 1 : 0;
    int cnt = m0 + m1 + m2 + m3;
    int s = cnt;
#pragma unroll
    for (int off = 1; off < 32; off <<= 1) {
        int u = __shfl_up_sync(0xffffffffu, s, off);
        if (lane >= off) s += u;
    }
    if (lane == 31) wscan[w] = s;
    __syncthreads();
    int wbase = 0;
#pragma unroll
    for (int i = 0; i < 8; i++) wbase += (i < w) ? wscan[i] : 0;
    int myExcl = wbase + s - cnt;
    if (prefT < nT || prefO < nO) {
        int tb2 = prefT + myExcl;
        int ob = prefO + t * 4 - myExcl;
        int p = sb * 1024 + t * 4;
        if (m0) { if (tb2 < nT) g_tinyIdx[tb2] = p; tb2++; } else { if (ob < nO) g_otherIdx[ob] = p; ob++; }
        p++;
        if (m1) { if (tb2 < nT) g_tinyIdx[tb2] = p; tb2++; } else { if (ob < nO) g_otherIdx[ob] = p; ob++; }
        p++;
        if (m2) { if (tb2 < nT) g_tinyIdx[tb2] = p; tb2++; } else { if (ob < nO) g_otherIdx[ob] = p; ob++; }
        p++;
        if (m3) { if (tb2 < nT) g_tinyIdx[tb2] = p; tb2++; } else { if (ob < nO) g_otherIdx[ob] = p; ob++; }
    }
    if (t == 0) {
        float g = sgrad[0] + sgrad[1] + sgrad[2] + sgrad[3]
                + sgrad[4] + sgrad[5] + sgrad[6] + sgrad[7];
        atomicAdd(&g_acc[17], (double)g);
    }
}

// ================ pass 3: gather + l2norm (4 rows/warp, batched MLP) ================
__global__ __launch_bounds__(256) void k_gather(const float* __restrict__ pf) {
    int warp = threadIdx.x >> 5, lane = threadIdx.x & 31;
    int rbase = (blockIdx.x * 8 + warp) * 4;
    int nT = g_nT, nO = g_nO;
    int idx[4]; float v[4];
#pragma unroll
    for (int k = 0; k < 4; k++) {
        int r = rbase + k;
        int id = -1;
        if (r < MAXT) { if (r < nT) id = g_tinyIdx[r]; }
        else { int j = r - MAXT; if (j < nO) id = g_otherIdx[j]; }
        idx[k] = id;
    }
#pragma unroll
    for (int k = 0; k < 4; k++) {
        int id = idx[k];
        v[k] = (id >= 0) ? pf[(size_t)((id >> 18) * CF + lane) * HW + (id & (HW - 1))] : 0.f;
    }
#pragma unroll
    for (int k = 0; k < 4; k++) {
        float sq = v[k] * v[k];
        WSUM(sq)
        g_cols[(rbase + k) * CF + lane] = v[k] / fmaxf(sqrtf(sq), 1e-12f);   // invalid rows -> 0
    }
}

// ================ pass 4: tiny contrastive — 128x64 tiles, 128 threads, 8x8 micro ================
// grid (8 row-tiles, 80 col-tiles) = 640 blocks. 128 thr = 16(ty) x 8(tx).
__global__ __launch_bounds__(128) void k_tinyloss() {
    __shared__ float As[32][128];      // [k][row] 16KB
    __shared__ float Bs[32][64];       // [k][col] 8KB
    __shared__ float red[128][8];      // row-sum staging 4KB
    int tid = threadIdx.x;
    int rbase = blockIdx.x * 128;
    int cbase = blockIdx.y * 64;

    // stage A (128 rows) transposed: 1024 float4, 8 reps
#pragma unroll
    for (int rep = 0; rep < 8; rep++) {
        int idx = rep * 128 + tid;
        int r = idx >> 3, q = idx & 7;
        float4 va = *(const float4*)(g_cols + (rbase + r) * CF + q * 4);
        As[q * 4 + 0][r] = va.x; As[q * 4 + 1][r] = va.y;
        As[q * 4 + 2][r] = va.z; As[q * 4 + 3][r] = va.w;
    }
    // stage B (64 cols) transposed: 512 float4, 4 reps
#pragma unroll
    for (int rep = 0; rep < 4; rep++) {
        int idx = rep * 128 + tid;
        int r = idx >> 3, q = idx & 7;
        float4 vb = *(const float4*)(g_cols + (cbase + r) * CF + q * 4);
        Bs[q * 4 + 0][r] = vb.x; Bs[q * 4 + 1][r] = vb.y;
        Bs[q * 4 + 2][r] = vb.z; Bs[q * 4 + 3][r] = vb.w;
    }
    __syncthreads();

    int tx = tid & 7, ty = tid >> 3;
    unsigned long long acc[8][4];
#pragma unroll
    for (int i = 0; i < 8; i++)
#pragma unroll
        for (int j = 0; j < 4; j++) acc[i][j] = 0ull;

#pragma unroll 8
    for (int k = 0; k < 32; k++) {
        float4 aA = *(const float4*)&As[k][ty * 8];
        float4 aB = *(const float4*)&As[k][ty * 8 + 4];
        ulonglong2 b0 = *(const ulonglong2*)&Bs[k][tx * 8];
        ulonglong2 b1 = *(const ulonglong2*)&Bs[k][tx * 8 + 4];
        float av[8] = {aA.x, aA.y, aA.z, aA.w, aB.x, aB.y, aB.z, aB.w};
#pragma unroll
        for (int i = 0; i < 8; i++) {
            unsigned long long a2;
            PACK2(a2, av[i]);
            FMA2(acc[i][0], a2, b0.x);
            FMA2(acc[i][1], a2, b0.y);
            FMA2(acc[i][2], a2, b1.x);
            FMA2(acc[i][3], a2, b1.y);
        }
    }

    // epilogue: single-MUFU exp + row-sum of this thread's 8 cols
#pragma unroll
    for (int i = 0; i < 8; i++) {
        float rs = 0.f;
#pragma unroll
        for (int j = 0; j < 4; j++) {
            float2 f = *(float2*)&acc[i][j];
            rs += ex2(fmaf(f.x, K10, -K10));
            rs += ex2(fmaf(f.y, K10, -K10));
        }
        red[ty * 8 + i][tx] = rs;
    }
    __syncthreads();
    {
        const float4* rp = (const float4*)&red[tid][0];
        float4 s0 = rp[0], s1 = rp[1];
        float tot = ((s0.x + s0.y) + (s0.z + s0.w)) + ((s1.x + s1.y) + (s1.z + s1.w));
        g_part1[blockIdx.y * MAXT + rbase + tid] = tot;
    }
}

// ================ pass 5: final (parallelized cls contrastive) ================
__global__ __launch_bounds__(1024) void k_final(const float* __restrict__ emb,
                                                const int* __restrict__ lab,
                                                float* __restrict__ out) {
    __shared__ float e[Bsz * Dd];
    __shared__ float dotm[Bsz * Bsz];
    __shared__ float red[32];
    __shared__ float s_per[Bsz], s_bce[Bsz];
    __shared__ int s_has[Bsz];
    int t = threadIdx.x, lane = t & 31, w = t >> 5;
    int nT = g_nT, nO = g_nO;

    float per = 0.f;
    if (t < nT) {
        float sT = 0.f, sO = 0.f;
#pragma unroll
        for (int c = 0; c < 16; c++)  sT += g_part1[c * MAXT + t];    // col tiles 0..15 = tiny (16*64=1024)
#pragma unroll 16
        for (int c = 16; c < NCH; c++) sO += g_part1[c * MAXT + t];   // col tiles 16..79 = other
        const float cz = ex2(-K10);
        sT -= 1.0f + (float)(MAXT - nT) * cz;
        sO -= (float)(MAXO - nO) * cz;
        sT = fmaxf(sT, 1e-30f);
        per = log1pf(sO / sT);
    }

    for (int i = t; i < Bsz * Dd; i += 1024) e[i] = emb[i];
    __syncthreads();
    if (t < 256) {
        float sq = 0.f;
        for (int k = lane; k < Dd; k += 32) { float v = e[w * Dd + k]; sq += v * v; }
        WSUM(sq)
        float inv = 1.0f / fmaxf(sqrtf(sq), 1e-12f);
        for (int k = lane; k < Dd; k += 32) e[w * Dd + k] *= inv;
    }
    __syncthreads();
    if (t < 256) {
        for (int j = 0; j < Bsz; j++) {
            float d = 0.f;
            for (int k = lane; k < Dd; k += 32) d += e[w * Dd + k] * e[j * Dd + k];
            WSUM(d)
            if (lane == 0) dotm[w * Bsz + j] = d;
        }
    }
    __syncthreads();

    // parallel cls contrastive: thread i < 8 owns row i
    if (t < Bsz) {
        int i = t;
        int Li = lab[i];
        float sP = 0.f, sA = 0.f, bce = 0.f;
        int has = 0;
#pragma unroll
        for (int j = 0; j < Bsz; j++) {
            if (j == i) continue;
            float dv = dotm[i * Bsz + j];
            float wE = ex2(fmaf(dv, K10, -K10));
            sA += wE;
            bool pos = (Li == lab[j]);
            if (pos) { has = 1; sP += wE; }
            float cosv = fminf(fmaxf(dv, -1.0f), 1.0f);
            float p01 = (cosv + 1.0f) * 0.5f;
            float l1 = fmaxf(__logf(p01), -100.0f);
            float l2 = fmaxf(__logf(1.0f - p01), -100.0f);
            bce += pos ? -l1 : -l2;
        }
        s_per[i] = has ? __logf(sA / sP) : 0.f;
        s_has[i] = has;
        s_bce[i] = bce;
    }

    WSUM(per)
    if (lane == 0) red[w] = per;
    __syncthreads();

    if (t == 0) {
        float tinySum = 0.f;
        for (int i = 0; i < 32; i++) tinySum += red[i];

        float per_sum = 0.f, bce_sum = 0.f;
        int nvalid = 0;
        for (int i = 0; i < Bsz; i++) {
            per_sum += s_per[i];
            bce_sum += s_bce[i];
            nvalid += s_has[i];
        }
        float clsv = (nvalid > 0) ? per_sum / (float)nvalid : bce_sum / 56.0f;

        double N = (double)BHW;
        double ce = g_acc[0] / N;
        double fo = g_acc[1] / N;
        double gr = g_acc[17] / N;
        double ds = 0.0;
        for (int c = 0; c < Ccls; c++) {
            double inter = g_acc[7 + c];
            double den = g_acc[2 + c] + g_acc[12 + c];
            ds += (2.0 * inter + 1e-6) / (den + 1e-6);
        }
        double dice = 1.0 - ds / 5.0;
        double tiny = 0.0;
        if (g_enabled) tiny = (double)tinySum / (double)(nT > 0 ? nT : 1);
        out[0] = (float)(ce + dice + fo + gr + tiny + (double)clsv);
    }
}

// ---------------- launch ----------------
extern "C" void kernel_launch(void* const* d_in, const int* in_sizes, int n_in,
                              void* d_out, int out_size) {
    const float* logits  = (const float*)d_in[0];
    const int*   targets = (const int*)d_in[1];
    const float* pf      = (const float*)d_in[2];
    const float* emb     = (const float*)d_in[3];
    const int*   clab    = (const int*)d_in[4];
    float* out = (float*)d_out;

    k_stats<<<NSCAN, 256>>>(logits, targets);
    k_ss<<<NSCAN, 256>>>(targets);
    k_gather<<<160, 256>>>(pf);
    k_tinyloss<<<dim3(8, NCH), 128>>>();
    k_final<<<1, 1024>>>(emb, clab, out);
}